// round 3
// baseline (speedup 1.0000x reference)
#include <cuda_runtime.h>
#include <cuda_bf16.h>

#define JNT 24
#define EPSF 1e-6f
#define SH_C0 0.28209479177387814f
#define SH_C1 0.4886025119029199f
#define C20 ( 1.0925484305920792f)
#define C21 (-1.0925484305920792f)
#define C22 ( 0.31539156525252005f)
#define C23 (-1.0925484305920792f)
#define C24 ( 0.5462742152960396f)

__device__ __forceinline__ float frcp(float x) {
    float r; asm("rcp.approx.ftz.f32 %0, %1;" : "=f"(r) : "f"(x)); return r;
}

// Shared: 6 float4 per joint
//  q0..q2 : rows 0..2 of T (t*0, t*1, t*2, t*3)
//  q3     : (L0, L1, L2, base)   base = SH_C0*f0 + 0.5 - C22*f6
//  q4     : (f1', f2', f3', f4') pre-scaled
//  q5     : (f5', f6'', f7', f8')  f6'' = 3*C22*f6
__global__ __launch_bounds__(256, 4)
void shcaster_kernel(const float* __restrict__ xyz,
                     const float* __restrict__ vdir,
                     const float* __restrict__ T,   // [J,4,4]
                     const float* __restrict__ F,   // [J,9]
                     const float* __restrict__ L,   // [J,3]
                     float* __restrict__ out,       // [2*N*3]
                     int N)
{
    __shared__ __align__(16) float4 sJ[JNT][6];

    const int tid = threadIdx.x;
    if (tid < JNT * 6) {
        const int j = tid / 6, k = tid % 6;
        float4 q;
        if (k < 3) {
            const float* r = T + j * 16 + k * 4;
            q = make_float4(r[0], r[1], r[2], r[3]);
        } else if (k == 3) {
            const float base = fmaf(SH_C0, F[j * 9 + 0], 0.5f) - C22 * F[j * 9 + 6];
            q = make_float4(L[j * 3 + 0], L[j * 3 + 1], L[j * 3 + 2], base);
        } else if (k == 4) {
            q = make_float4(-SH_C1 * F[j * 9 + 1],
                             SH_C1 * F[j * 9 + 2],
                            -SH_C1 * F[j * 9 + 3],
                             C20   * F[j * 9 + 4]);
        } else {
            q = make_float4( C21        * F[j * 9 + 5],
                             3.f * C22  * F[j * 9 + 6],
                             C23        * F[j * 9 + 7],
                             C24        * F[j * 9 + 8]);
        }
        sJ[j][k] = q;
    }
    __syncthreads();

    const int stride = gridDim.x * blockDim.x;
    for (int i = blockIdx.x * blockDim.x + tid; i < N; i += stride) {
        const float x0 = xyz[3 * i + 0];
        const float x1 = xyz[3 * i + 1];
        const float x2 = xyz[3 * i + 2];
        const float v0 = vdir[3 * i + 0];
        const float v1 = vdir[3 * i + 1];
        const float v2 = vdir[3 * i + 2];

        float wsum = 0.f;
        float s0 = 0.f, s1 = 0.f, s2 = 0.f;
        float m00 = 0.f, m01 = 0.f, m02 = 0.f;
        float m10 = 0.f, m11 = 0.f, m12 = 0.f;
        float m20 = 0.f, m21 = 0.f, m22 = 0.f;

#pragma unroll
        for (int j = 0; j < JNT; j++) {
            const float4 q0 = sJ[j][0];
            const float4 q1 = sJ[j][1];
            const float4 q2 = sJ[j][2];
            const float4 q3 = sJ[j][3];
            const float4 q4 = sJ[j][4];
            const float4 q5 = sJ[j][5];

            // a = R x + t
            const float a0 = fmaf(q0.x, x0, fmaf(q0.y, x1, fmaf(q0.z, x2, q0.w)));
            const float a1 = fmaf(q1.x, x0, fmaf(q1.y, x1, fmaf(q1.z, x2, q1.w)));
            const float a2 = fmaf(q2.x, x0, fmaf(q2.y, x1, fmaf(q2.z, x2, q2.w)));

            // d = L - a
            const float d0 = q3.x - a0;
            const float d1 = q3.y - a1;
            const float d2 = q3.z - a2;

            const float l2  = fmaf(d0, d0, fmaf(d1, d1, d2 * d2));
            const float inv = rsqrtf(l2);
            const float inv2 = inv * inv;

            // SH dot evaluated in unnormalized d-space:
            // rad = base + (lin . d) * inv + quad(d) * inv^2
            const float linD = fmaf(q4.x, d1, fmaf(q4.y, d2, q4.z * d0));
            const float xy = d0 * d1;
            const float yz = d1 * d2;
            const float xz = d0 * d2;
            const float zz = d2 * d2;
            const float pm = (d0 - d1) * (d0 + d1);   // x^2 - y^2
            const float quadD = fmaf(q4.w, xy,
                                fmaf(q5.x, yz,
                                fmaf(q5.y, zz,
                                fmaf(q5.z, xz, q5.w * pm))));
            const float rad = fmaf(linD, inv, fmaf(quadD, inv2, q3.w));

            // weight: r = max(relu(rad), EPS) = max(rad, EPS)
            const float r = fmaxf(rad, EPSF);
            const float len = l2 * inv;
            const float w = fmaxf(fmaf(-len, frcp(r), 1.0f), 0.f);

            wsum += w;
            s0 = fmaf(w, a0, s0);
            s1 = fmaf(w, a1, s1);
            s2 = fmaf(w, a2, s2);
            m00 = fmaf(w, q0.x, m00); m01 = fmaf(w, q0.y, m01); m02 = fmaf(w, q0.z, m02);
            m10 = fmaf(w, q1.x, m10); m11 = fmaf(w, q1.y, m11); m12 = fmaf(w, q1.z, m12);
            m20 = fmaf(w, q2.x, m20); m21 = fmaf(w, q2.y, m21); m22 = fmaf(w, q2.z, m22);
        }

        const float ic = frcp(fmaxf(wsum, EPSF));
        const bool valid = wsum > EPSF;

        const float o0 = valid ? s0 * ic : x0;
        const float o1 = valid ? s1 * ic : x1;
        const float o2 = valid ? s2 * ic : x2;

        const float e0 = fmaf(m00, v0, fmaf(m01, v1, m02 * v2)) * ic;
        const float e1 = fmaf(m10, v0, fmaf(m11, v1, m12 * v2)) * ic;
        const float e2 = fmaf(m20, v0, fmaf(m21, v1, m22 * v2)) * ic;
        const float g0 = valid ? e0 : v0;
        const float g1 = valid ? e1 : v1;
        const float g2 = valid ? e2 : v2;

        out[3 * i + 0] = o0;
        out[3 * i + 1] = o1;
        out[3 * i + 2] = o2;
        float* out2 = out + (size_t)3 * N;
        out2[3 * i + 0] = g0;
        out2[3 * i + 1] = g1;
        out2[3 * i + 2] = g2;
    }
}

extern "C" void kernel_launch(void* const* d_in, const int* in_sizes, int n_in,
                              void* d_out, int out_size)
{
    const float* xyz  = (const float*)d_in[0];
    const float* vdir = (const float*)d_in[1];
    const float* T    = (const float*)d_in[2];
    const float* F    = (const float*)d_in[3];
    const float* L    = (const float*)d_in[4];
    float* out        = (float*)d_out;

    const int N = in_sizes[0] / 3;
    const int threads = 256;
    // Single resident wave: 152 SMs x 4 blocks/SM (launch_bounds guarantees 4/SM)
    int blocks = 152 * 4;
    const int maxBlocks = (N + threads - 1) / threads;
    if (blocks > maxBlocks) blocks = maxBlocks;
    shcaster_kernel<<<blocks, threads>>>(xyz, vdir, T, F, L, out, N);
}

// round 4
// speedup vs baseline: 8.3750x; 8.3750x over previous
#include <cuda_runtime.h>
#include <cuda_bf16.h>

#define JNT 24
#define EPSF 1e-6f
#define SH_C0 0.28209479177387814f
#define SH_C1 0.4886025119029199f
#define C20 ( 1.0925484305920792f)
#define C21 (-1.0925484305920792f)
#define C22 ( 0.31539156525252005f)
#define C23 (-1.0925484305920792f)
#define C24 ( 0.5462742152960396f)

__device__ __forceinline__ float frcp(float x) {
    float r; asm("rcp.approx.ftz.f32 %0, %1;" : "=f"(r) : "f"(x)); return r;
}

// Shared: 6 float4 per joint
//  q0..q2 : rows 0..2 of T (t*0, t*1, t*2, t*3)
//  q3     : (L0, L1, L2, base)   base = SH_C0*f0 + 0.5 - C22*f6
//  q4     : (f1', f2', f3', f4') pre-scaled
//  q5     : (f5', f6'', f7', f8')  f6'' = 3*C22*f6
__global__ __launch_bounds__(256)
void shcaster_kernel(const float* __restrict__ xyz,
                     const float* __restrict__ vdir,
                     const float* __restrict__ T,   // [J,4,4]
                     const float* __restrict__ F,   // [J,9]
                     const float* __restrict__ L,   // [J,3]
                     float* __restrict__ out,       // [2*N*3]
                     int N)
{
    __shared__ __align__(16) float4 sJ[JNT][6];

    const int tid = threadIdx.x;
    if (tid < JNT * 6) {
        const int j = tid / 6, k = tid % 6;
        float4 q;
        if (k < 3) {
            const float* r = T + j * 16 + k * 4;
            q = make_float4(r[0], r[1], r[2], r[3]);
        } else if (k == 3) {
            const float base = fmaf(SH_C0, F[j * 9 + 0], 0.5f) - C22 * F[j * 9 + 6];
            q = make_float4(L[j * 3 + 0], L[j * 3 + 1], L[j * 3 + 2], base);
        } else if (k == 4) {
            q = make_float4(-SH_C1 * F[j * 9 + 1],
                             SH_C1 * F[j * 9 + 2],
                            -SH_C1 * F[j * 9 + 3],
                             C20   * F[j * 9 + 4]);
        } else {
            q = make_float4( C21        * F[j * 9 + 5],
                             3.f * C22  * F[j * 9 + 6],
                             C23        * F[j * 9 + 7],
                             C24        * F[j * 9 + 8]);
        }
        sJ[j][k] = q;
    }
    __syncthreads();

    const int i = blockIdx.x * blockDim.x + tid;
    if (i >= N) return;

    const float x0 = xyz[3 * i + 0];
    const float x1 = xyz[3 * i + 1];
    const float x2 = xyz[3 * i + 2];
    const float v0 = vdir[3 * i + 0];
    const float v1 = vdir[3 * i + 1];
    const float v2 = vdir[3 * i + 2];

    float wsum = 0.f;
    float s0 = 0.f, s1 = 0.f, s2 = 0.f;
    float m00 = 0.f, m01 = 0.f, m02 = 0.f;
    float m10 = 0.f, m11 = 0.f, m12 = 0.f;
    float m20 = 0.f, m21 = 0.f, m22 = 0.f;

#pragma unroll
    for (int j = 0; j < JNT; j++) {
        const float4 q0 = sJ[j][0];
        const float4 q1 = sJ[j][1];
        const float4 q2 = sJ[j][2];
        const float4 q3 = sJ[j][3];
        const float4 q4 = sJ[j][4];
        const float4 q5 = sJ[j][5];

        // a = R x + t
        const float a0 = fmaf(q0.x, x0, fmaf(q0.y, x1, fmaf(q0.z, x2, q0.w)));
        const float a1 = fmaf(q1.x, x0, fmaf(q1.y, x1, fmaf(q1.z, x2, q1.w)));
        const float a2 = fmaf(q2.x, x0, fmaf(q2.y, x1, fmaf(q2.z, x2, q2.w)));

        // d = L - a
        const float d0 = q3.x - a0;
        const float d1 = q3.y - a1;
        const float d2 = q3.z - a2;

        const float l2  = fmaf(d0, d0, fmaf(d1, d1, d2 * d2));
        const float inv = rsqrtf(l2);
        const float inv2 = inv * inv;

        // SH dot in unnormalized d-space:
        // rad = base + (lin . d) * inv + quad(d) * inv^2
        const float linD = fmaf(q4.x, d1, fmaf(q4.y, d2, q4.z * d0));
        const float xy = d0 * d1;
        const float yz = d1 * d2;
        const float xz = d0 * d2;
        const float zz = d2 * d2;
        const float pm = (d0 - d1) * (d0 + d1);   // x^2 - y^2
        const float quadD = fmaf(q4.w, xy,
                            fmaf(q5.x, yz,
                            fmaf(q5.y, zz,
                            fmaf(q5.z, xz, q5.w * pm))));
        const float rad = fmaf(linD, inv, fmaf(quadD, inv2, q3.w));

        // weight: r = max(relu(rad), EPS) = max(rad, EPS)
        const float r = fmaxf(rad, EPSF);
        const float len = l2 * inv;
        const float w = fmaxf(fmaf(-len, frcp(r), 1.0f), 0.f);

        wsum += w;
        s0 = fmaf(w, a0, s0);
        s1 = fmaf(w, a1, s1);
        s2 = fmaf(w, a2, s2);
        m00 = fmaf(w, q0.x, m00); m01 = fmaf(w, q0.y, m01); m02 = fmaf(w, q0.z, m02);
        m10 = fmaf(w, q1.x, m10); m11 = fmaf(w, q1.y, m11); m12 = fmaf(w, q1.z, m12);
        m20 = fmaf(w, q2.x, m20); m21 = fmaf(w, q2.y, m21); m22 = fmaf(w, q2.z, m22);
    }

    const float ic = frcp(fmaxf(wsum, EPSF));
    const bool valid = wsum > EPSF;

    const float o0 = valid ? s0 * ic : x0;
    const float o1 = valid ? s1 * ic : x1;
    const float o2 = valid ? s2 * ic : x2;

    const float e0 = fmaf(m00, v0, fmaf(m01, v1, m02 * v2)) * ic;
    const float e1 = fmaf(m10, v0, fmaf(m11, v1, m12 * v2)) * ic;
    const float e2 = fmaf(m20, v0, fmaf(m21, v1, m22 * v2)) * ic;
    const float g0 = valid ? e0 : v0;
    const float g1 = valid ? e1 : v1;
    const float g2 = valid ? e2 : v2;

    out[3 * i + 0] = o0;
    out[3 * i + 1] = o1;
    out[3 * i + 2] = o2;
    float* out2 = out + (size_t)3 * N;
    out2[3 * i + 0] = g0;
    out2[3 * i + 1] = g1;
    out2[3 * i + 2] = g2;
}

extern "C" void kernel_launch(void* const* d_in, const int* in_sizes, int n_in,
                              void* d_out, int out_size)
{
    const float* xyz  = (const float*)d_in[0];
    const float* vdir = (const float*)d_in[1];
    const float* T    = (const float*)d_in[2];
    const float* F    = (const float*)d_in[3];
    const float* L    = (const float*)d_in[4];
    float* out        = (float*)d_out;

    const int N = in_sizes[0] / 3;
    const int threads = 256;
    const int blocks = (N + threads - 1) / threads;
    shcaster_kernel<<<blocks, threads>>>(xyz, vdir, T, F, L, out, N);
}